// round 12
// baseline (speedup 1.0000x reference)
#include <cuda_runtime.h>
#include <cuda_fp16.h>
#include <cstdint>

#define NPTS  2000000
#define TILES 15625          // 2,000,000 / 128 exactly

// dynamic shared layout (bytes)
#define XS_OFF  0            // half [128][120]  (stride 240B, LDSM conflict-free)
#define W1_OFF  30720        // half [64][120]   W1S[j][k] = W1[k][j], k pad 105->112 zeros
#define W2_OFF  46080        // half [64][72]    W2S[j][k] = W2[k][j]
#define W3_OFF  55296        // half [8][72]     W3hS[n][k] = W3[k*3+n] (n<3), else 0
#define B1P_OFF 56448        // uint32 [32] packed f16 bias pairs, idx = nt*4+tig
#define B2P_OFF 56576        // uint32 [32]
#define SMEM_BYTES 56704

__device__ __forceinline__ uint32_t pk(float a, float b) {
    __half2 h = __floats2half2_rn(a, b);
    return *reinterpret_cast<uint32_t*>(&h);
}

__device__ __forceinline__ float2 upk(uint32_t v) {
    __half2 h = *reinterpret_cast<__half2*>(&v);
    return __half22float2(h);
}

__device__ __forceinline__ void sts8(__half* p,
    float a, float b, float c, float d, float e, float f, float g, float h) {
    uint4 u;
    u.x = pk(a, b); u.y = pk(c, d); u.z = pk(e, f); u.w = pk(g, h);
    *reinterpret_cast<uint4*>(p) = u;
}

// sin of a packed f16 pair -> packed f16 pair
__device__ __forceinline__ uint32_t sinpk(uint32_t v) {
    float2 z = upk(v);
    return pk(__sinf(z.x), __sinf(z.y));
}

// f16 accumulate
__device__ __forceinline__ void mma16816h(uint32_t* c,
    const uint32_t* a, uint32_t b0, uint32_t b1) {
    asm volatile(
        "mma.sync.aligned.m16n8k16.row.col.f16.f16.f16.f16 "
        "{%0,%1}, {%2,%3,%4,%5}, {%6,%7}, {%0,%1};\n"
        : "+r"(c[0]), "+r"(c[1])
        : "r"(a[0]), "r"(a[1]), "r"(a[2]), "r"(a[3]), "r"(b0), "r"(b1));
}

// f32 accumulate (layer 3)
__device__ __forceinline__ void mma16816f(float* c,
    const uint32_t* a, uint32_t b0, uint32_t b1) {
    asm volatile(
        "mma.sync.aligned.m16n8k16.row.col.f32.f16.f16.f32 "
        "{%0,%1,%2,%3}, {%4,%5,%6,%7}, {%8,%9}, {%0,%1,%2,%3};\n"
        : "+f"(c[0]), "+f"(c[1]), "+f"(c[2]), "+f"(c[3])
        : "r"(a[0]), "r"(a[1]), "r"(a[2]), "r"(a[3]), "r"(b0), "r"(b1));
}

__device__ __forceinline__ void ldsm4(uint32_t* r, uint32_t addr) {
    asm volatile(
        "ldmatrix.sync.aligned.m8n8.x4.shared.b16 {%0,%1,%2,%3}, [%4];\n"
        : "=r"(r[0]), "=r"(r[1]), "=r"(r[2]), "=r"(r[3]) : "r"(addr));
}

// Rolling, low-liveness feature generation: writes all 112 f16 cols for `row`.
__device__ __forceinline__ void write_features(
    const float* __restrict__ bases, const float* __restrict__ normals,
    const float* __restrict__ enc, int row, __half* xr,
    float& bxO, float& byO, float& bzO)
{
    const float4* ep = reinterpret_cast<const float4*>(enc + (size_t)row * 20);
    float4 e0 = ep[0], e1 = ep[1];
    sts8(xr + 0, e0.x, e0.y, e0.z, e0.w, e1.x, e1.y, e1.z, e1.w);
    float4 e2 = ep[2], e3 = ep[3];
    sts8(xr + 8, e2.x, e2.y, e2.z, e2.w, e3.x, e3.y, e3.z, e3.w);
    float4 e4 = ep[4];
    float bx = bases[row * 3 + 0], by = bases[row * 3 + 1], bz = bases[row * 3 + 2];

    float s0x, c0x, s0y, c0y, s0z, c0z;
    __sincosf(2.f * bx, &s0x, &c0x);
    __sincosf(2.f * by, &s0y, &c0y);
    __sincosf(2.f * bz, &s0z, &c0z);
    sts8(xr + 16, e4.x, e4.y, e4.z, e4.w, bx, by, bz, s0x);

    float s1x = 2.f*s0x*c0x, c1x = 1.f-2.f*s0x*s0x;
    float s1y = 2.f*s0y*c0y, c1y = 1.f-2.f*s0y*s0y;
    float s1z = 2.f*s0z*c0z, c1z = 1.f-2.f*s0z*s0z;
    sts8(xr + 24, s0y, s0z, c0x, c0y, c0z, s1x, s1y, s1z);

    float s2x = 2.f*s1x*c1x, c2x = 1.f-2.f*s1x*s1x;
    float s2y = 2.f*s1y*c1y, c2y = 1.f-2.f*s1y*s1y;
    float s2z = 2.f*s1z*c1z, c2z = 1.f-2.f*s1z*s1z;
    sts8(xr + 32, c1x, c1y, c1z, s2x, s2y, s2z, c2x, c2y);

    float s3x = 2.f*s2x*c2x, c3x = 1.f-2.f*s2x*s2x;
    float s3y = 2.f*s2y*c2y, c3y = 1.f-2.f*s2y*s2y;
    float s3z = 2.f*s2z*c2z, c3z = 1.f-2.f*s2z*s2z;
    float s4x = 2.f*s3x*c3x, c4x = 1.f-2.f*s3x*s3x;
    sts8(xr + 40, c2z, s3x, s3y, s3z, c3x, c3y, c3z, s4x);

    float s4y = 2.f*s3y*c3y, c4y = 1.f-2.f*s3y*s3y;
    float s4z = 2.f*s3z*c3z, c4z = 1.f-2.f*s3z*s3z;
    float s5x = 2.f*s4x*c4x, c5x = 1.f-2.f*s4x*s4x;
    float s5y = 2.f*s4y*c4y, c5y = 1.f-2.f*s4y*s4y;
    float s5z = 2.f*s4z*c4z, c5z = 1.f-2.f*s4z*s4z;
    sts8(xr + 48, s4y, s4z, c4x, c4y, c4z, s5x, s5y, s5z);

    float s6x = 2.f*s5x*c5x, c6x = 1.f-2.f*s5x*s5x;
    float s6y = 2.f*s5y*c5y, c6y = 1.f-2.f*s5y*s5y;
    float s6z = 2.f*s5z*c5z, c6z = 1.f-2.f*s5z*s5z;
    sts8(xr + 56, c5x, c5y, c5z, s6x, s6y, s6z, c6x, c6y);

    float n0 = normals[row * 2 + 0], n1 = normals[row * 2 + 1];
    float s7x = 2.f*s6x*c6x, c7x = 1.f-2.f*s6x*s6x;
    float s7y = 2.f*s6y*c6y, c7y = 1.f-2.f*s6y*s6y;
    float s7z = 2.f*s6z*c6z, c7z = 1.f-2.f*s6z*s6z;
    sts8(xr + 64, c6z, s7x, s7y, s7z, c7x, c7y, c7z, n0);

    const float V1 = 0.80073740291680f;   // exp(-50/225)
    const float V2 = 0.64118038843357f;   // exp(-100/225)
    {
        float E = __expf(-50.f * n0 * n0);
        float r = __expf(6.66666667f * n0) * V1;
        float a0=E; E*=r; r*=V2; float a1=E; E*=r; r*=V2;
        float a2=E; E*=r; r*=V2; float a3=E; E*=r; r*=V2;
        float a4=E; E*=r; r*=V2; float a5=E; E*=r; r*=V2;
        float a6=E; E*=r; r*=V2;
        sts8(xr + 72, n1, a0, a1, a2, a3, a4, a5, a6);
        a0=E; E*=r; r*=V2; a1=E; E*=r; r*=V2; a2=E; E*=r; r*=V2;
        a3=E; E*=r; r*=V2; a4=E; E*=r; r*=V2; a5=E; E*=r; r*=V2;
        a6=E; E*=r; r*=V2; float a7=E; E*=r;                   // E = bl0[15]
        sts8(xr + 80, a0, a1, a2, a3, a4, a5, a6, a7);

        float F = __expf(-50.f * n1 * n1);
        float q = __expf(6.66666667f * n1) * V1;
        a0=F; F*=q; q*=V2; a1=F; F*=q; q*=V2; a2=F; F*=q; q*=V2;
        a3=F; F*=q; q*=V2; a4=F; F*=q; q*=V2; a5=F; F*=q; q*=V2;
        a6=F; F*=q; q*=V2;
        sts8(xr + 88, E, a0, a1, a2, a3, a4, a5, a6);
        a0=F; F*=q; q*=V2; a1=F; F*=q; q*=V2; a2=F; F*=q; q*=V2;
        a3=F; F*=q; q*=V2; a4=F; F*=q; q*=V2; a5=F; F*=q; q*=V2;
        a6=F; F*=q; q*=V2; a7=F; F*=q;
        sts8(xr + 96, a0, a1, a2, a3, a4, a5, a6, a7);
        sts8(xr + 104, F, 0.f, 0.f, 0.f, 0.f, 0.f, 0.f, 0.f);
    }
    bxO = bx; byO = by; bzO = bz;
}

__global__ void __launch_bounds__(128, 4)
fused_encode_mlp(const float* __restrict__ bases,
                 const float* __restrict__ normals,
                 const float* __restrict__ enc,
                 const float* __restrict__ W1, const float* __restrict__ b1,
                 const float* __restrict__ W2, const float* __restrict__ b2,
                 const float* __restrict__ W3, const float* __restrict__ b3,
                 float* __restrict__ out)
{
    extern __shared__ char smem[];
    __half* XS   = reinterpret_cast<__half*>(smem + XS_OFF);
    __half* W1S  = reinterpret_cast<__half*>(smem + W1_OFF);
    __half* W2S  = reinterpret_cast<__half*>(smem + W2_OFF);
    __half* W3hS = reinterpret_cast<__half*>(smem + W3_OFF);
    uint32_t* B1P = reinterpret_cast<uint32_t*>(smem + B1P_OFF);
    uint32_t* B2P = reinterpret_cast<uint32_t*>(smem + B2P_OFF);

    const int tid  = threadIdx.x;
    const int lane = tid & 31;
    const int wp   = tid >> 5;
    const int g    = lane >> 2;
    const int tig  = lane & 3;
    const int warpRow = wp * 32;

    // ---- stage weights once per CTA ----
    for (int i = tid; i < 64 * 120; i += 128) W1S[i] = __float2half(0.f);
    for (int i = tid; i < 8 * 72; i += 128)   W3hS[i] = __float2half(0.f);
    __syncthreads();
    for (int i = tid; i < 105 * 64; i += 128) {
        int k = i >> 6, j = i & 63;
        W1S[j * 120 + k] = __float2half(W1[i]);
    }
    for (int i = tid; i < 64 * 64; i += 128) {
        int k = i >> 6, j = i & 63;
        W2S[j * 72 + k] = __float2half(W2[i]);
    }
    if (tid < 64) {
        int k = tid;
        W3hS[0 * 72 + k] = __float2half(W3[k * 3 + 0]);
        W3hS[1 * 72 + k] = __float2half(W3[k * 3 + 1]);
        W3hS[2 * 72 + k] = __float2half(W3[k * 3 + 2]);
    }
    if (tid < 32) {
        int nt = tid >> 2, tg = tid & 3;
        B1P[tid] = pk(b1[nt * 8 + tg * 2], b1[nt * 8 + tg * 2 + 1]);
        B2P[tid] = pk(b2[nt * 8 + tg * 2], b2[nt * 8 + tg * 2 + 1]);
    }
    __syncthreads();

    // ---- ldmatrix addresses ----
    const uint32_t xs_b = (uint32_t)__cvta_generic_to_shared(XS);
    const uint32_t w1_b = (uint32_t)__cvta_generic_to_shared(W1S);
    const uint32_t w2_b = (uint32_t)__cvta_generic_to_shared(W2S);
    const uint32_t w3_b = (uint32_t)__cvta_generic_to_shared(W3hS);

    const int aRowIn = (lane & 7) + ((lane >> 3) & 1) * 8;
    const int aCol   = ((lane >> 4) & 1) * 16;
    uint32_t baseA0 = xs_b + (uint32_t)((warpRow + aRowIn) * 240 + aCol);
    uint32_t baseA1 = baseA0 + 16u * 240u;

    const int bRowIn = (lane & 7) + ((lane >> 4) & 1) * 8;
    const int bCol   = ((lane >> 3) & 1) * 16;
    const uint32_t bB1 = w1_b + (uint32_t)(bRowIn * 240 + bCol);
    const uint32_t bB2 = w2_b + (uint32_t)(bRowIn * 144 + bCol);

    // ---- hoist W3 B-fragments (8 regs) ----
    uint32_t B3f[4][2];
    {
        uint32_t baseB3 = w3_b + (uint32_t)((lane & 7) * 144 + bCol);
        #pragma unroll
        for (int kk = 0; kk < 4; kk++) {
            uint32_t t[4];
            ldsm4(t, baseB3 + kk * 32);
            B3f[kk][0] = t[0]; B3f[kk][1] = t[1];
        }
    }

    const float i3a = (tig == 0) ? b3[0] : (tig == 1) ? b3[2] : 0.f;   // C col 2*tig
    const float i3b = (tig == 0) ? b3[1] : 0.f;                        // C col 2*tig+1

    __half* xr = XS + tid * 120;

    // ---- prologue: features for first tile ----
    float bxC, byC, bzC;
    write_features(bases, normals, enc, blockIdx.x * 128 + tid, xr, bxC, byC, bzC);

    for (int tile = blockIdx.x; tile < TILES; tile += gridDim.x) {
        __syncwarp();   // features STS (prologue / previous iteration) visible

        // ================= layer 1: f16 acc, bias-init =================
        uint32_t acc[2][8][2];
        #pragma unroll
        for (int nt = 0; nt < 8; nt++) {
            uint32_t bw = B1P[nt * 4 + tig];
            acc[0][nt][0] = bw; acc[0][nt][1] = bw;
            acc[1][nt][0] = bw; acc[1][nt][1] = bw;
        }
        #pragma unroll
        for (int kk = 0; kk < 7; kk++) {
            uint32_t aA[4], aB[4];
            ldsm4(aA, baseA0 + kk * 32);
            ldsm4(aB, baseA1 + kk * 32);
            #pragma unroll
            for (int p = 0; p < 4; p++) {
                uint32_t b[4];
                ldsm4(b, bB1 + p * (16 * 240) + kk * 32);
                mma16816h(acc[0][2 * p],     aA, b[0], b[1]);
                mma16816h(acc[0][2 * p + 1], aA, b[2], b[3]);
                mma16816h(acc[1][2 * p],     aB, b[0], b[1]);
                mma16816h(acc[1][2 * p + 1], aB, b[2], b[3]);
            }
        }
        __syncwarp();   // A-LDSM done -> XS free for next tile's features

        // ================= features(t+1) -> XS (independent stream; scheduler
        // interleaves its LDG/FMA/STS chain with the JIT l2/l3 below) ==========
        float bxN, byN, bzN;
        {
            int ntile = tile + gridDim.x;
            if (ntile >= TILES) ntile = TILES - 1;    // clamped dummy, deterministic
            write_features(bases, normals, enc, ntile * 128 + tid, xr, bxN, byN, bzN);
        }

        // ================= layer 2: JIT sins pipelined one kk-step ahead ========
        uint32_t ac2[2][8][2];
        #pragma unroll
        for (int nt = 0; nt < 8; nt++) {
            uint32_t bw = B2P[nt * 4 + tig];
            ac2[0][nt][0] = bw; ac2[0][nt][1] = bw;
            ac2[1][nt][0] = bw; ac2[1][nt][1] = bw;
        }
        uint32_t ahC[2][2][2];
        #pragma unroll
        for (int mt = 0; mt < 2; mt++)
            #pragma unroll
            for (int q = 0; q < 2; q++) {
                ahC[mt][q][0] = sinpk(acc[mt][q][0]);
                ahC[mt][q][1] = sinpk(acc[mt][q][1]);
            }
        #pragma unroll
        for (int kk = 0; kk < 4; kk++) {
            uint32_t ahN[2][2][2];
            if (kk < 3) {           // MUFU stream for kk+1
                #pragma unroll
                for (int mt = 0; mt < 2; mt++)
                    #pragma unroll
                    for (int q = 0; q < 2; q++) {
                        ahN[mt][q][0] = sinpk(acc[mt][2 * kk + 2 + q][0]);
                        ahN[mt][q][1] = sinpk(acc[mt][2 * kk + 2 + q][1]);
                    }
            }
            #pragma unroll
            for (int p = 0; p < 4; p++) {   // tensor stream for kk
                uint32_t b[4];
                ldsm4(b, bB2 + p * (16 * 144) + kk * 32);
                #pragma unroll
                for (int mt = 0; mt < 2; mt++) {
                    uint32_t a[4] = { ahC[mt][0][0], ahC[mt][0][1],
                                      ahC[mt][1][0], ahC[mt][1][1] };
                    mma16816h(ac2[mt][2 * p],     a, b[0], b[1]);
                    mma16816h(ac2[mt][2 * p + 1], a, b[2], b[3]);
                }
            }
            if (kk < 3) {
                #pragma unroll
                for (int mt = 0; mt < 2; mt++)
                    #pragma unroll
                    for (int q = 0; q < 2; q++) {
                        ahC[mt][q][0] = ahN[mt][q][0];
                        ahC[mt][q][1] = ahN[mt][q][1];
                    }
            }
        }

        // ================= layer 3: same JIT pipeline over ac2 =================
        float c0[4] = { i3a, i3b, i3a, i3b };
        float c1[4] = { i3a, i3b, i3a, i3b };
        #pragma unroll
        for (int mt = 0; mt < 2; mt++)
            #pragma unroll
            for (int q = 0; q < 2; q++) {
                ahC[mt][q][0] = sinpk(ac2[mt][q][0]);
                ahC[mt][q][1] = sinpk(ac2[mt][q][1]);
            }
        #pragma unroll
        for (int kk = 0; kk < 4; kk++) {
            uint32_t ahN[2][2][2];
            if (kk < 3) {
                #pragma unroll
                for (int mt = 0; mt < 2; mt++)
                    #pragma unroll
                    for (int q = 0; q < 2; q++) {
                        ahN[mt][q][0] = sinpk(ac2[mt][2 * kk + 2 + q][0]);
                        ahN[mt][q][1] = sinpk(ac2[mt][2 * kk + 2 + q][1]);
                    }
            }
            {
                uint32_t a0[4] = { ahC[0][0][0], ahC[0][0][1], ahC[0][1][0], ahC[0][1][1] };
                uint32_t a1[4] = { ahC[1][0][0], ahC[1][0][1], ahC[1][1][0], ahC[1][1][1] };
                mma16816f(c0, a0, B3f[kk][0], B3f[kk][1]);
                mma16816f(c1, a1, B3f[kk][0], B3f[kk][1]);
            }
            if (kk < 3) {
                #pragma unroll
                for (int mt = 0; mt < 2; mt++)
                    #pragma unroll
                    for (int q = 0; q < 2; q++) {
                        ahC[mt][q][0] = ahN[mt][q][0];
                        ahC[mt][q][1] = ahN[mt][q][1];
                    }
            }
        }

        // ================= residual + store =================
        #pragma unroll
        for (int mt = 0; mt < 2; mt++) {
            const float* c = (mt == 0) ? c0 : c1;
            float bxA = __shfl_sync(0xffffffffu, bxC, mt * 16 + g);
            float byA = __shfl_sync(0xffffffffu, byC, mt * 16 + g);
            float bzA = __shfl_sync(0xffffffffu, bzC, mt * 16 + g);
            float bxB = __shfl_sync(0xffffffffu, bxC, mt * 16 + g + 8);
            float byB = __shfl_sync(0xffffffffu, byC, mt * 16 + g + 8);
            float bzB = __shfl_sync(0xffffffffu, bzC, mt * 16 + g + 8);

            int rA = tile * 128 + warpRow + mt * 16 + g;
            int rB = rA + 8;
            if (tig == 0) {      // C cols 0,1 = out.x, out.y
                out[rA * 3 + 0] = bxA + c[0];
                out[rA * 3 + 1] = byA + c[1];
                out[rB * 3 + 0] = bxB + c[2];
                out[rB * 3 + 1] = byB + c[3];
            } else if (tig == 1) {  // C col 2 = out.z
                out[rA * 3 + 2] = bzA + c[0];
                out[rB * 3 + 2] = bzB + c[2];
            }
        }

        // rotate pipeline registers
        bxC = bxN; byC = byN; bzC = bzN;
    }
}

extern "C" void kernel_launch(void* const* d_in, const int* in_sizes, int n_in,
                              void* d_out, int out_size) {
    const float* bases   = (const float*)d_in[0];
    const float* normals = (const float*)d_in[1];
    const float* enc     = (const float*)d_in[2];
    const float* W1      = (const float*)d_in[3];
    const float* b1      = (const float*)d_in[4];
    const float* W2      = (const float*)d_in[5];
    const float* b2      = (const float*)d_in[6];
    const float* W3      = (const float*)d_in[7];
    const float* b3      = (const float*)d_in[8];
    float* out = (float*)d_out;

    cudaFuncSetAttribute(fused_encode_mlp,
                         cudaFuncAttributeMaxDynamicSharedMemorySize, SMEM_BYTES);

    // persistent: 148 SMs x 4 CTAs (smem-limited, 16 warps/SM)
    fused_encode_mlp<<<592, 128, SMEM_BYTES>>>(bases, normals, enc,
                                               W1, b1, W2, b2, W3, b3, out);
}

// round 13
// speedup vs baseline: 1.0154x; 1.0154x over previous
#include <cuda_runtime.h>
#include <cuda_fp16.h>
#include <cstdint>

#define NPTS  2000000
#define TILES 15625          // 2,000,000 / 128 exactly

// dynamic shared layout (bytes)
#define XS_OFF  0            // half [128][120]  (stride 240B, LDSM conflict-free)
#define W1_OFF  30720        // half [64][120]   W1S[j][k] = W1[k][j], k pad 105->112 zeros
#define W2_OFF  46080        // half [64][72]    W2S[j][k] = W2[k][j]
#define W3_OFF  55296        // half [8][72]     W3hS[n][k] = W3[k*3+n] (n<3), else 0
#define B1P_OFF 56448        // uint32 [32] packed f16 bias pairs, idx = nt*4+tig
#define B2P_OFF 56576        // uint32 [32]
#define SMEM_BYTES 56704

__device__ __forceinline__ uint32_t pk(float a, float b) {
    __half2 h = __floats2half2_rn(a, b);
    return *reinterpret_cast<uint32_t*>(&h);
}

__device__ __forceinline__ float2 upk(uint32_t v) {
    __half2 h = *reinterpret_cast<__half2*>(&v);
    return __half22float2(h);
}

__device__ __forceinline__ void sts8(__half* p,
    float a, float b, float c, float d, float e, float f, float g, float h) {
    uint4 u;
    u.x = pk(a, b); u.y = pk(c, d); u.z = pk(e, f); u.w = pk(g, h);
    *reinterpret_cast<uint4*>(p) = u;
}

// sin of a packed f16 pair -> packed f16 pair
__device__ __forceinline__ uint32_t sinpk(uint32_t v) {
    float2 z = upk(v);
    return pk(__sinf(z.x), __sinf(z.y));
}

// f16 accumulate
__device__ __forceinline__ void mma16816h(uint32_t* c,
    const uint32_t* a, uint32_t b0, uint32_t b1) {
    asm volatile(
        "mma.sync.aligned.m16n8k16.row.col.f16.f16.f16.f16 "
        "{%0,%1}, {%2,%3,%4,%5}, {%6,%7}, {%0,%1};\n"
        : "+r"(c[0]), "+r"(c[1])
        : "r"(a[0]), "r"(a[1]), "r"(a[2]), "r"(a[3]), "r"(b0), "r"(b1));
}

// f32 accumulate (layer 3)
__device__ __forceinline__ void mma16816f(float* c,
    const uint32_t* a, uint32_t b0, uint32_t b1) {
    asm volatile(
        "mma.sync.aligned.m16n8k16.row.col.f32.f16.f16.f32 "
        "{%0,%1,%2,%3}, {%4,%5,%6,%7}, {%8,%9}, {%0,%1,%2,%3};\n"
        : "+f"(c[0]), "+f"(c[1]), "+f"(c[2]), "+f"(c[3])
        : "r"(a[0]), "r"(a[1]), "r"(a[2]), "r"(a[3]), "r"(b0), "r"(b1));
}

__device__ __forceinline__ void ldsm4(uint32_t* r, uint32_t addr) {
    asm volatile(
        "ldmatrix.sync.aligned.m8n8.x4.shared.b16 {%0,%1,%2,%3}, [%4];\n"
        : "=r"(r[0]), "=r"(r[1]), "=r"(r[2]), "=r"(r[3]) : "r"(addr));
}

__global__ void __launch_bounds__(128, 4)
fused_encode_mlp(const float* __restrict__ bases,
                 const float* __restrict__ normals,
                 const float* __restrict__ enc,
                 const float* __restrict__ W1, const float* __restrict__ b1,
                 const float* __restrict__ W2, const float* __restrict__ b2,
                 const float* __restrict__ W3, const float* __restrict__ b3,
                 float* __restrict__ out)
{
    extern __shared__ char smem[];
    __half* XS   = reinterpret_cast<__half*>(smem + XS_OFF);
    __half* W1S  = reinterpret_cast<__half*>(smem + W1_OFF);
    __half* W2S  = reinterpret_cast<__half*>(smem + W2_OFF);
    __half* W3hS = reinterpret_cast<__half*>(smem + W3_OFF);
    uint32_t* B1P = reinterpret_cast<uint32_t*>(smem + B1P_OFF);
    uint32_t* B2P = reinterpret_cast<uint32_t*>(smem + B2P_OFF);

    const int tid  = threadIdx.x;
    const int lane = tid & 31;
    const int wp   = tid >> 5;
    const int g    = lane >> 2;
    const int tig  = lane & 3;
    const int warpRow = wp * 32;

    // ---- stage weights once per CTA ----
    for (int i = tid; i < 64 * 120; i += 128) W1S[i] = __float2half(0.f);
    for (int i = tid; i < 8 * 72; i += 128)   W3hS[i] = __float2half(0.f);
    __syncthreads();
    for (int i = tid; i < 105 * 64; i += 128) {
        int k = i >> 6, j = i & 63;
        W1S[j * 120 + k] = __float2half(W1[i]);
    }
    for (int i = tid; i < 64 * 64; i += 128) {
        int k = i >> 6, j = i & 63;
        W2S[j * 72 + k] = __float2half(W2[i]);
    }
    if (tid < 64) {
        int k = tid;
        W3hS[0 * 72 + k] = __float2half(W3[k * 3 + 0]);
        W3hS[1 * 72 + k] = __float2half(W3[k * 3 + 1]);
        W3hS[2 * 72 + k] = __float2half(W3[k * 3 + 2]);
    }
    if (tid < 32) {
        int nt = tid >> 2, tg = tid & 3;
        B1P[tid] = pk(b1[nt * 8 + tg * 2], b1[nt * 8 + tg * 2 + 1]);
        B2P[tid] = pk(b2[nt * 8 + tg * 2], b2[nt * 8 + tg * 2 + 1]);
    }
    __syncthreads();

    // ---- ldmatrix addresses ----
    const uint32_t xs_b = (uint32_t)__cvta_generic_to_shared(XS);
    const uint32_t w1_b = (uint32_t)__cvta_generic_to_shared(W1S);
    const uint32_t w2_b = (uint32_t)__cvta_generic_to_shared(W2S);
    const uint32_t w3_b = (uint32_t)__cvta_generic_to_shared(W3hS);

    const int aRowIn = (lane & 7) + ((lane >> 3) & 1) * 8;
    const int aCol   = ((lane >> 4) & 1) * 16;
    uint32_t baseA0 = xs_b + (uint32_t)((warpRow + aRowIn) * 240 + aCol);
    uint32_t baseA1 = baseA0 + 16u * 240u;

    const int bRowIn = (lane & 7) + ((lane >> 4) & 1) * 8;
    const int bCol   = ((lane >> 3) & 1) * 16;
    const uint32_t bB1 = w1_b + (uint32_t)(bRowIn * 240 + bCol);
    const uint32_t bB2 = w2_b + (uint32_t)(bRowIn * 144 + bCol);

    // ---- hoist W3 B-fragments (8 regs) ----
    uint32_t B3f[4][2];
    {
        uint32_t baseB3 = w3_b + (uint32_t)((lane & 7) * 144 + bCol);
        #pragma unroll
        for (int kk = 0; kk < 4; kk++) {
            uint32_t t[4];
            ldsm4(t, baseB3 + kk * 32);
            B3f[kk][0] = t[0]; B3f[kk][1] = t[1];
        }
    }

    const float i3a = (tig == 0) ? b3[0] : (tig == 1) ? b3[2] : 0.f;   // C col 2*tig
    const float i3b = (tig == 0) ? b3[1] : 0.f;                        // C col 2*tig+1

    __half* xr = XS + tid * 120;

    for (int tile = blockIdx.x; tile < TILES; tile += gridDim.x) {
        const int row = tile * 128 + tid;

        // ================= phase A features: cols 0..63 =================
        const float4* ep = reinterpret_cast<const float4*>(enc + (size_t)row * 20);
        float4 e0 = ep[0], e1 = ep[1];
        sts8(xr + 0, e0.x, e0.y, e0.z, e0.w, e1.x, e1.y, e1.z, e1.w);
        float4 e2 = ep[2], e3 = ep[3];
        sts8(xr + 8, e2.x, e2.y, e2.z, e2.w, e3.x, e3.y, e3.z, e3.w);
        float4 e4 = ep[4];
        float bx = bases[row * 3 + 0], by = bases[row * 3 + 1], bz = bases[row * 3 + 2];
        float n0 = normals[row * 2 + 0], n1 = normals[row * 2 + 1];   // issue LDG early

        float s0x, c0x, s0y, c0y, s0z, c0z;
        __sincosf(2.f * bx, &s0x, &c0x);
        __sincosf(2.f * by, &s0y, &c0y);
        __sincosf(2.f * bz, &s0z, &c0z);
        sts8(xr + 16, e4.x, e4.y, e4.z, e4.w, bx, by, bz, s0x);

        float s1x = 2.f*s0x*c0x, c1x = 1.f-2.f*s0x*s0x;
        float s1y = 2.f*s0y*c0y, c1y = 1.f-2.f*s0y*s0y;
        float s1z = 2.f*s0z*c0z, c1z = 1.f-2.f*s0z*s0z;
        sts8(xr + 24, s0y, s0z, c0x, c0y, c0z, s1x, s1y, s1z);

        float s2x = 2.f*s1x*c1x, c2x = 1.f-2.f*s1x*s1x;
        float s2y = 2.f*s1y*c1y, c2y = 1.f-2.f*s1y*s1y;
        float s2z = 2.f*s1z*c1z, c2z = 1.f-2.f*s1z*s1z;
        sts8(xr + 32, c1x, c1y, c1z, s2x, s2y, s2z, c2x, c2y);

        float s3x = 2.f*s2x*c2x, c3x = 1.f-2.f*s2x*s2x;
        float s3y = 2.f*s2y*c2y, c3y = 1.f-2.f*s2y*s2y;
        float s3z = 2.f*s2z*c2z, c3z = 1.f-2.f*s2z*s2z;
        float s4x = 2.f*s3x*c3x, c4x = 1.f-2.f*s3x*s3x;
        sts8(xr + 40, c2z, s3x, s3y, s3z, c3x, c3y, c3z, s4x);

        float s4y = 2.f*s3y*c3y, c4y = 1.f-2.f*s3y*s3y;
        float s4z = 2.f*s3z*c3z, c4z = 1.f-2.f*s3z*s3z;
        float s5x = 2.f*s4x*c4x, c5x = 1.f-2.f*s4x*s4x;
        float s5y = 2.f*s4y*c4y, c5y = 1.f-2.f*s4y*s4y;
        float s5z = 2.f*s4z*c4z, c5z = 1.f-2.f*s4z*s4z;
        sts8(xr + 48, s4y, s4z, c4x, c4y, c4z, s5x, s5y, s5z);

        float s6x = 2.f*s5x*c5x, c6x = 1.f-2.f*s5x*s5x;
        float s6y = 2.f*s5y*c5y, c6y = 1.f-2.f*s5y*s5y;
        float s6z = 2.f*s5z*c5z, c6z = 1.f-2.f*s5z*s5z;
        sts8(xr + 56, c5x, c5y, c5z, s6x, s6y, s6z, c6x, c6y);

        __syncwarp();   // phase-A cols visible to all lanes

        // ================= layer 1 part 1 (kk=0..3, cols 0..63)  ‖  phase B ======
        uint32_t acc[2][8][2];
        #pragma unroll
        for (int nt = 0; nt < 8; nt++) {
            uint32_t bw = B1P[nt * 4 + tig];
            acc[0][nt][0] = bw; acc[0][nt][1] = bw;
            acc[1][nt][0] = bw; acc[1][nt][1] = bw;
        }
        #pragma unroll
        for (int kk = 0; kk < 4; kk++) {
            uint32_t aA[4], aB[4];
            ldsm4(aA, baseA0 + kk * 32);
            ldsm4(aB, baseA1 + kk * 32);
            #pragma unroll
            for (int p = 0; p < 4; p++) {
                uint32_t b[4];
                ldsm4(b, bB1 + p * (16 * 240) + kk * 32);
                mma16816h(acc[0][2 * p],     aA, b[0], b[1]);
                mma16816h(acc[0][2 * p + 1], aA, b[2], b[3]);
                mma16816h(acc[1][2 * p],     aB, b[0], b[1]);
                mma16816h(acc[1][2 * p + 1], aB, b[2], b[3]);
            }
        }

        // ---- phase B features (cols 64..111): independent of kk0-3 MMAs above;
        //      scheduler interleaves MUFU/FMA/STS with the HMMA stream ----
        {
            float s7x = 2.f*s6x*c6x, c7x = 1.f-2.f*s6x*s6x;
            float s7y = 2.f*s6y*c6y, c7y = 1.f-2.f*s6y*s6y;
            float s7z = 2.f*s6z*c6z, c7z = 1.f-2.f*s6z*s6z;
            sts8(xr + 64, c6z, s7x, s7y, s7z, c7x, c7y, c7z, n0);

            const float V1 = 0.80073740291680f;   // exp(-50/225)
            const float V2 = 0.64118038843357f;   // exp(-100/225)
            float E = __expf(-50.f * n0 * n0);
            float r = __expf(6.66666667f * n0) * V1;
            float a0=E; E*=r; r*=V2; float a1=E; E*=r; r*=V2;
            float a2=E; E*=r; r*=V2; float a3=E; E*=r; r*=V2;
            float a4=E; E*=r; r*=V2; float a5=E; E*=r; r*=V2;
            float a6=E; E*=r; r*=V2;
            sts8(xr + 72, n1, a0, a1, a2, a3, a4, a5, a6);
            a0=E; E*=r; r*=V2; a1=E; E*=r; r*=V2; a2=E; E*=r; r*=V2;
            a3=E; E*=r; r*=V2; a4=E; E*=r; r*=V2; a5=E; E*=r; r*=V2;
            a6=E; E*=r; r*=V2; float a7=E; E*=r;                   // E = bl0[15]
            sts8(xr + 80, a0, a1, a2, a3, a4, a5, a6, a7);

            float F = __expf(-50.f * n1 * n1);
            float q = __expf(6.66666667f * n1) * V1;
            a0=F; F*=q; q*=V2; a1=F; F*=q; q*=V2; a2=F; F*=q; q*=V2;
            a3=F; F*=q; q*=V2; a4=F; F*=q; q*=V2; a5=F; F*=q; q*=V2;
            a6=F; F*=q; q*=V2;
            sts8(xr + 88, E, a0, a1, a2, a3, a4, a5, a6);
            a0=F; F*=q; q*=V2; a1=F; F*=q; q*=V2; a2=F; F*=q; q*=V2;
            a3=F; F*=q; q*=V2; a4=F; F*=q; q*=V2; a5=F; F*=q; q*=V2;
            a6=F; F*=q; q*=V2; a7=F; F*=q;
            sts8(xr + 96, a0, a1, a2, a3, a4, a5, a6, a7);
            sts8(xr + 104, F, 0.f, 0.f, 0.f, 0.f, 0.f, 0.f, 0.f);
        }
        __syncwarp();   // phase-B cols visible

        // ================= layer 1 part 2 (kk=4..6, cols 64..111) =================
        #pragma unroll
        for (int kk = 4; kk < 7; kk++) {
            uint32_t aA[4], aB[4];
            ldsm4(aA, baseA0 + kk * 32);
            ldsm4(aB, baseA1 + kk * 32);
            #pragma unroll
            for (int p = 0; p < 4; p++) {
                uint32_t b[4];
                ldsm4(b, bB1 + p * (16 * 240) + kk * 32);
                mma16816h(acc[0][2 * p],     aA, b[0], b[1]);
                mma16816h(acc[0][2 * p + 1], aA, b[2], b[3]);
                mma16816h(acc[1][2 * p],     aB, b[0], b[1]);
                mma16816h(acc[1][2 * p + 1], aB, b[2], b[3]);
            }
        }

        // ================= layer 2: JIT sins pipelined one kk-step ahead ========
        uint32_t ac2[2][8][2];
        #pragma unroll
        for (int nt = 0; nt < 8; nt++) {
            uint32_t bw = B2P[nt * 4 + tig];
            ac2[0][nt][0] = bw; ac2[0][nt][1] = bw;
            ac2[1][nt][0] = bw; ac2[1][nt][1] = bw;
        }
        uint32_t ahC[2][2][2];
        #pragma unroll
        for (int mt = 0; mt < 2; mt++)
            #pragma unroll
            for (int q = 0; q < 2; q++) {
                ahC[mt][q][0] = sinpk(acc[mt][q][0]);
                ahC[mt][q][1] = sinpk(acc[mt][q][1]);
            }
        #pragma unroll
        for (int kk = 0; kk < 4; kk++) {
            uint32_t ahN[2][2][2];
            if (kk < 3) {           // MUFU stream for kk+1
                #pragma unroll
                for (int mt = 0; mt < 2; mt++)
                    #pragma unroll
                    for (int q = 0; q < 2; q++) {
                        ahN[mt][q][0] = sinpk(acc[mt][2 * kk + 2 + q][0]);
                        ahN[mt][q][1] = sinpk(acc[mt][2 * kk + 2 + q][1]);
                    }
            }
            #pragma unroll
            for (int p = 0; p < 4; p++) {   // tensor stream for kk
                uint32_t b[4];
                ldsm4(b, bB2 + p * (16 * 144) + kk * 32);
                #pragma unroll
                for (int mt = 0; mt < 2; mt++) {
                    uint32_t a[4] = { ahC[mt][0][0], ahC[mt][0][1],
                                      ahC[mt][1][0], ahC[mt][1][1] };
                    mma16816h(ac2[mt][2 * p],     a, b[0], b[1]);
                    mma16816h(ac2[mt][2 * p + 1], a, b[2], b[3]);
                }
            }
            if (kk < 3) {
                #pragma unroll
                for (int mt = 0; mt < 2; mt++)
                    #pragma unroll
                    for (int q = 0; q < 2; q++) {
                        ahC[mt][q][0] = ahN[mt][q][0];
                        ahC[mt][q][1] = ahN[mt][q][1];
                    }
            }
        }

        // ================= layer 3: same JIT pipeline over ac2 =================
        float c0[4] = { i3a, i3b, i3a, i3b };
        float c1[4] = { i3a, i3b, i3a, i3b };
        #pragma unroll
        for (int mt = 0; mt < 2; mt++)
            #pragma unroll
            for (int q = 0; q < 2; q++) {
                ahC[mt][q][0] = sinpk(ac2[mt][q][0]);
                ahC[mt][q][1] = sinpk(ac2[mt][q][1]);
            }
        #pragma unroll
        for (int kk = 0; kk < 4; kk++) {
            uint32_t ahN[2][2][2];
            if (kk < 3) {
                #pragma unroll
                for (int mt = 0; mt < 2; mt++)
                    #pragma unroll
                    for (int q = 0; q < 2; q++) {
                        ahN[mt][q][0] = sinpk(ac2[mt][2 * kk + 2 + q][0]);
                        ahN[mt][q][1] = sinpk(ac2[mt][2 * kk + 2 + q][1]);
                    }
            }
            {
                uint32_t a0[4] = { ahC[0][0][0], ahC[0][0][1], ahC[0][1][0], ahC[0][1][1] };
                uint32_t a1[4] = { ahC[1][0][0], ahC[1][0][1], ahC[1][1][0], ahC[1][1][1] };
                mma16816f(c0, a0, B3f[kk][0], B3f[kk][1]);
                mma16816f(c1, a1, B3f[kk][0], B3f[kk][1]);
            }
            if (kk < 3) {
                #pragma unroll
                for (int mt = 0; mt < 2; mt++)
                    #pragma unroll
                    for (int q = 0; q < 2; q++) {
                        ahC[mt][q][0] = ahN[mt][q][0];
                        ahC[mt][q][1] = ahN[mt][q][1];
                    }
            }
        }

        // ================= residual + store =================
        #pragma unroll
        for (int mt = 0; mt < 2; mt++) {
            const float* c = (mt == 0) ? c0 : c1;
            float bxA = __shfl_sync(0xffffffffu, bx, mt * 16 + g);
            float byA = __shfl_sync(0xffffffffu, by, mt * 16 + g);
            float bzA = __shfl_sync(0xffffffffu, bz, mt * 16 + g);
            float bxB = __shfl_sync(0xffffffffu, bx, mt * 16 + g + 8);
            float byB = __shfl_sync(0xffffffffu, by, mt * 16 + g + 8);
            float bzB = __shfl_sync(0xffffffffu, bz, mt * 16 + g + 8);

            int rA = tile * 128 + warpRow + mt * 16 + g;
            int rB = rA + 8;
            if (tig == 0) {      // C cols 0,1 = out.x, out.y
                out[rA * 3 + 0] = bxA + c[0];
                out[rA * 3 + 1] = byA + c[1];
                out[rB * 3 + 0] = bxB + c[2];
                out[rB * 3 + 1] = byB + c[3];
            } else if (tig == 1) {  // C col 2 = out.z
                out[rA * 3 + 2] = bzA + c[0];
                out[rB * 3 + 2] = bzB + c[2];
            }
        }
        __syncwarp();   // all XS reads done before next tile's phase A overwrites
    }
}

extern "C" void kernel_launch(void* const* d_in, const int* in_sizes, int n_in,
                              void* d_out, int out_size) {
    const float* bases   = (const float*)d_in[0];
    const float* normals = (const float*)d_in[1];
    const float* enc     = (const float*)d_in[2];
    const float* W1      = (const float*)d_in[3];
    const float* b1      = (const float*)d_in[4];
    const float* W2      = (const float*)d_in[5];
    const float* b2      = (const float*)d_in[6];
    const float* W3      = (const float*)d_in[7];
    const float* b3      = (const float*)d_in[8];
    float* out = (float*)d_out;

    cudaFuncSetAttribute(fused_encode_mlp,
                         cudaFuncAttributeMaxDynamicSharedMemorySize, SMEM_BYTES);

    // persistent: 148 SMs x 4 CTAs (smem-limited, 16 warps/SM)
    fused_encode_mlp<<<592, 128, SMEM_BYTES>>>(bases, normals, enc,
                                               W1, b1, W2, b2, W3, b3, out);
}

// round 14
// speedup vs baseline: 1.0457x; 1.0298x over previous
#include <cuda_runtime.h>
#include <cuda_fp16.h>
#include <cstdint>

#define NPTS  2000000
#define TILES 15625          // 2,000,000 / 128 exactly

// dynamic shared layout (bytes)
#define XS_OFF  0            // half [128][120]  (stride 240B, LDSM conflict-free)
#define W1_OFF  30720        // half [64][120]   W1S[j][k] = W1[k][j], k pad 105->112 zeros
#define W2_OFF  46080        // half [64][72]    W2S[j][k] = W2[k][j]
#define W3_OFF  55296        // half [8][72]     W3hS[n][k] = W3[k*3+n] (n<3), else 0
#define B1P_OFF 56448        // uint32 [32] packed f16 bias pairs, idx = nt*4+tig
#define B2P_OFF 56576        // uint32 [32]
#define SMEM_BYTES 56704

__device__ __forceinline__ uint32_t pk(float a, float b) {
    __half2 h = __floats2half2_rn(a, b);
    return *reinterpret_cast<uint32_t*>(&h);
}

__device__ __forceinline__ float2 upk(uint32_t v) {
    __half2 h = *reinterpret_cast<__half2*>(&v);
    return __half22float2(h);
}

__device__ __forceinline__ void sts8(__half* p,
    float a, float b, float c, float d, float e, float f, float g, float h) {
    uint4 u;
    u.x = pk(a, b); u.y = pk(c, d); u.z = pk(e, f); u.w = pk(g, h);
    *reinterpret_cast<uint4*>(p) = u;
}

// sin of a packed f16 pair -> packed f16 pair
__device__ __forceinline__ uint32_t sinpk(uint32_t v) {
    float2 z = upk(v);
    return pk(__sinf(z.x), __sinf(z.y));
}

// f16 accumulate
__device__ __forceinline__ void mma16816h(uint32_t* c,
    const uint32_t* a, uint32_t b0, uint32_t b1) {
    asm volatile(
        "mma.sync.aligned.m16n8k16.row.col.f16.f16.f16.f16 "
        "{%0,%1}, {%2,%3,%4,%5}, {%6,%7}, {%0,%1};\n"
        : "+r"(c[0]), "+r"(c[1])
        : "r"(a[0]), "r"(a[1]), "r"(a[2]), "r"(a[3]), "r"(b0), "r"(b1));
}

// f32 accumulate (layer 3)
__device__ __forceinline__ void mma16816f(float* c,
    const uint32_t* a, uint32_t b0, uint32_t b1) {
    asm volatile(
        "mma.sync.aligned.m16n8k16.row.col.f32.f16.f16.f32 "
        "{%0,%1,%2,%3}, {%4,%5,%6,%7}, {%8,%9}, {%0,%1,%2,%3};\n"
        : "+f"(c[0]), "+f"(c[1]), "+f"(c[2]), "+f"(c[3])
        : "r"(a[0]), "r"(a[1]), "r"(a[2]), "r"(a[3]), "r"(b0), "r"(b1));
}

__device__ __forceinline__ void ldsm4(uint32_t* r, uint32_t addr) {
    asm volatile(
        "ldmatrix.sync.aligned.m8n8.x4.shared.b16 {%0,%1,%2,%3}, [%4];\n"
        : "=r"(r[0]), "=r"(r[1]), "=r"(r[2]), "=r"(r[3]) : "r"(addr));
}

__global__ void __launch_bounds__(128, 4)
fused_encode_mlp(const float* __restrict__ bases,
                 const float* __restrict__ normals,
                 const float* __restrict__ enc,
                 const float* __restrict__ W1, const float* __restrict__ b1,
                 const float* __restrict__ W2, const float* __restrict__ b2,
                 const float* __restrict__ W3, const float* __restrict__ b3,
                 float* __restrict__ out)
{
    extern __shared__ char smem[];
    __half* XS   = reinterpret_cast<__half*>(smem + XS_OFF);
    __half* W1S  = reinterpret_cast<__half*>(smem + W1_OFF);
    __half* W2S  = reinterpret_cast<__half*>(smem + W2_OFF);
    __half* W3hS = reinterpret_cast<__half*>(smem + W3_OFF);
    uint32_t* B1P = reinterpret_cast<uint32_t*>(smem + B1P_OFF);
    uint32_t* B2P = reinterpret_cast<uint32_t*>(smem + B2P_OFF);

    const int tid  = threadIdx.x;
    const int lane = tid & 31;
    const int wp   = tid >> 5;
    const int g    = lane >> 2;
    const int tig  = lane & 3;
    const int warpRow = wp * 32;

    // ---- stage weights once per CTA ----
    for (int i = tid; i < 64 * 120; i += 128) W1S[i] = __float2half(0.f);
    for (int i = tid; i < 8 * 72; i += 128)   W3hS[i] = __float2half(0.f);
    __syncthreads();
    for (int i = tid; i < 105 * 64; i += 128) {
        int k = i >> 6, j = i & 63;
        W1S[j * 120 + k] = __float2half(W1[i]);
    }
    for (int i = tid; i < 64 * 64; i += 128) {
        int k = i >> 6, j = i & 63;
        W2S[j * 72 + k] = __float2half(W2[i]);
    }
    if (tid < 64) {
        int k = tid;
        W3hS[0 * 72 + k] = __float2half(W3[k * 3 + 0]);
        W3hS[1 * 72 + k] = __float2half(W3[k * 3 + 1]);
        W3hS[2 * 72 + k] = __float2half(W3[k * 3 + 2]);
    }
    if (tid < 32) {
        int nt = tid >> 2, tg = tid & 3;
        B1P[tid] = pk(b1[nt * 8 + tg * 2], b1[nt * 8 + tg * 2 + 1]);
        B2P[tid] = pk(b2[nt * 8 + tg * 2], b2[nt * 8 + tg * 2 + 1]);
    }
    __syncthreads();

    // ---- ldmatrix addresses ----
    const uint32_t xs_b = (uint32_t)__cvta_generic_to_shared(XS);
    const uint32_t w1_b = (uint32_t)__cvta_generic_to_shared(W1S);
    const uint32_t w2_b = (uint32_t)__cvta_generic_to_shared(W2S);
    const uint32_t w3_b = (uint32_t)__cvta_generic_to_shared(W3hS);

    const int aRowIn = (lane & 7) + ((lane >> 3) & 1) * 8;
    const int aCol   = ((lane >> 4) & 1) * 16;
    uint32_t baseA0 = xs_b + (uint32_t)((warpRow + aRowIn) * 240 + aCol);
    uint32_t baseA1 = baseA0 + 16u * 240u;

    const int bRowIn = (lane & 7) + ((lane >> 4) & 1) * 8;
    const int bCol   = ((lane >> 3) & 1) * 16;
    const uint32_t bB1 = w1_b + (uint32_t)(bRowIn * 240 + bCol);
    const uint32_t bB2 = w2_b + (uint32_t)(bRowIn * 144 + bCol);

    // ---- hoist W3 B-fragments (8 regs) ----
    uint32_t B3f[4][2];
    {
        uint32_t baseB3 = w3_b + (uint32_t)((lane & 7) * 144 + bCol);
        #pragma unroll
        for (int kk = 0; kk < 4; kk++) {
            uint32_t t[4];
            ldsm4(t, baseB3 + kk * 32);
            B3f[kk][0] = t[0]; B3f[kk][1] = t[1];
        }
    }

    const float i3a = (tig == 0) ? b3[0] : (tig == 1) ? b3[2] : 0.f;   // C col 2*tig
    const float i3b = (tig == 0) ? b3[1] : 0.f;                        // C col 2*tig+1

    __half* xr = XS + tid * 120;

    // ================= warp-phase stagger (convoy breaker) =================
    // Co-resident CTAs are bid, bid+148, bid+296, bid+444; SMSP k hosts warp k
    // of all four. skew gives those 4 warps offsets of ~0/640/1280/1920 cyc
    // (tile period ~2950), de-phasing their tensor/MUFU/L1 bursts.
    // Deterministic; result sunk into this warp's own XS row, overwritten by
    // real features below.
    {
        const int skew = ((blockIdx.x / 148) + wp) & 3;
        uint32_t dacc[8];
        #pragma unroll
        for (int i = 0; i < 8; i++) dacc[i] = B1P[i * 4 + tig] + (uint32_t)lane;
        for (int d = 0; d < skew; d++) {
            uint32_t dc[2] = { dacc[0], dacc[1] };
            #pragma unroll
            for (int r = 0; r < 4; r++) {
                #pragma unroll
                for (int i = 0; i < 8; i++) dacc[i] = sinpk(dacc[i]);
                mma16816h(dc, dacc, dacc[4], dacc[5]);
                mma16816h(dc, dacc + 4, dacc[0], dacc[1]);
            }
            dacc[0] ^= dc[0]; dacc[1] ^= dc[1];
        }
        *reinterpret_cast<uint2*>(xr) = make_uint2(dacc[0], dacc[1]);  // DCE sink
    }

    for (int tile = blockIdx.x; tile < TILES; tile += gridDim.x) {
        const int row = tile * 128 + tid;

        // ================= features -> SMEM (fp16, cols 0..111) =================
        const float4* ep = reinterpret_cast<const float4*>(enc + (size_t)row * 20);
        float4 e0 = ep[0], e1 = ep[1];
        sts8(xr + 0, e0.x, e0.y, e0.z, e0.w, e1.x, e1.y, e1.z, e1.w);
        float4 e2 = ep[2], e3 = ep[3];
        sts8(xr + 8, e2.x, e2.y, e2.z, e2.w, e3.x, e3.y, e3.z, e3.w);
        float4 e4 = ep[4];
        float bx = bases[row * 3 + 0], by = bases[row * 3 + 1], bz = bases[row * 3 + 2];

        float s0x, c0x, s0y, c0y, s0z, c0z;
        __sincosf(2.f * bx, &s0x, &c0x);
        __sincosf(2.f * by, &s0y, &c0y);
        __sincosf(2.f * bz, &s0z, &c0z);
        sts8(xr + 16, e4.x, e4.y, e4.z, e4.w, bx, by, bz, s0x);

        float s1x = 2.f*s0x*c0x, c1x = 1.f-2.f*s0x*s0x;
        float s1y = 2.f*s0y*c0y, c1y = 1.f-2.f*s0y*s0y;
        float s1z = 2.f*s0z*c0z, c1z = 1.f-2.f*s0z*s0z;
        sts8(xr + 24, s0y, s0z, c0x, c0y, c0z, s1x, s1y, s1z);

        float s2x = 2.f*s1x*c1x, c2x = 1.f-2.f*s1x*s1x;
        float s2y = 2.f*s1y*c1y, c2y = 1.f-2.f*s1y*s1y;
        float s2z = 2.f*s1z*c1z, c2z = 1.f-2.f*s1z*s1z;
        sts8(xr + 32, c1x, c1y, c1z, s2x, s2y, s2z, c2x, c2y);

        float s3x = 2.f*s2x*c2x, c3x = 1.f-2.f*s2x*s2x;
        float s3y = 2.f*s2y*c2y, c3y = 1.f-2.f*s2y*s2y;
        float s3z = 2.f*s2z*c2z, c3z = 1.f-2.f*s2z*s2z;
        float s4x = 2.f*s3x*c3x, c4x = 1.f-2.f*s3x*s3x;
        sts8(xr + 40, c2z, s3x, s3y, s3z, c3x, c3y, c3z, s4x);

        float s4y = 2.f*s3y*c3y, c4y = 1.f-2.f*s3y*s3y;
        float s4z = 2.f*s3z*c3z, c4z = 1.f-2.f*s3z*s3z;
        float s5x = 2.f*s4x*c4x, c5x = 1.f-2.f*s4x*s4x;
        float s5y = 2.f*s4y*c4y, c5y = 1.f-2.f*s4y*s4y;
        float s5z = 2.f*s4z*c4z, c5z = 1.f-2.f*s4z*s4z;
        sts8(xr + 48, s4y, s4z, c4x, c4y, c4z, s5x, s5y, s5z);

        float s6x = 2.f*s5x*c5x, c6x = 1.f-2.f*s5x*s5x;
        float s6y = 2.f*s5y*c5y, c6y = 1.f-2.f*s5y*s5y;
        float s6z = 2.f*s5z*c5z, c6z = 1.f-2.f*s5z*s5z;
        sts8(xr + 56, c5x, c5y, c5z, s6x, s6y, s6z, c6x, c6y);

        float n0 = normals[row * 2 + 0], n1 = normals[row * 2 + 1];
        float s7x = 2.f*s6x*c6x, c7x = 1.f-2.f*s6x*s6x;
        float s7y = 2.f*s6y*c6y, c7y = 1.f-2.f*s6y*s6y;
        float s7z = 2.f*s6z*c6z, c7z = 1.f-2.f*s6z*s6z;
        sts8(xr + 64, c6z, s7x, s7y, s7z, c7x, c7y, c7z, n0);

        const float V1 = 0.80073740291680f;   // exp(-50/225)
        const float V2 = 0.64118038843357f;   // exp(-100/225)
        {
            float E = __expf(-50.f * n0 * n0);
            float r = __expf(6.66666667f * n0) * V1;
            float a0=E; E*=r; r*=V2; float a1=E; E*=r; r*=V2;
            float a2=E; E*=r; r*=V2; float a3=E; E*=r; r*=V2;
            float a4=E; E*=r; r*=V2; float a5=E; E*=r; r*=V2;
            float a6=E; E*=r; r*=V2;
            sts8(xr + 72, n1, a0, a1, a2, a3, a4, a5, a6);
            a0=E; E*=r; r*=V2; a1=E; E*=r; r*=V2; a2=E; E*=r; r*=V2;
            a3=E; E*=r; r*=V2; a4=E; E*=r; r*=V2; a5=E; E*=r; r*=V2;
            a6=E; E*=r; r*=V2; float a7=E; E*=r;                   // E = bl0[15]
            sts8(xr + 80, a0, a1, a2, a3, a4, a5, a6, a7);

            float F = __expf(-50.f * n1 * n1);
            float q = __expf(6.66666667f * n1) * V1;
            a0=F; F*=q; q*=V2; a1=F; F*=q; q*=V2; a2=F; F*=q; q*=V2;
            a3=F; F*=q; q*=V2; a4=F; F*=q; q*=V2; a5=F; F*=q; q*=V2;
            a6=F; F*=q; q*=V2;
            sts8(xr + 88, E, a0, a1, a2, a3, a4, a5, a6);
            a0=F; F*=q; q*=V2; a1=F; F*=q; q*=V2; a2=F; F*=q; q*=V2;
            a3=F; F*=q; q*=V2; a4=F; F*=q; q*=V2; a5=F; F*=q; q*=V2;
            a6=F; F*=q; q*=V2; a7=F; F*=q;
            sts8(xr + 96, a0, a1, a2, a3, a4, a5, a6, a7);
            sts8(xr + 104, F, 0.f, 0.f, 0.f, 0.f, 0.f, 0.f, 0.f);
        }

        __syncwarp();   // warp reads only its own 32 rows

        // ================= layer 1: f16 acc, bias-init =================
        uint32_t acc[2][8][2];
        #pragma unroll
        for (int nt = 0; nt < 8; nt++) {
            uint32_t bw = B1P[nt * 4 + tig];
            acc[0][nt][0] = bw; acc[0][nt][1] = bw;
            acc[1][nt][0] = bw; acc[1][nt][1] = bw;
        }
        #pragma unroll
        for (int kk = 0; kk < 7; kk++) {
            uint32_t aA[4], aB[4];
            ldsm4(aA, baseA0 + kk * 32);
            ldsm4(aB, baseA1 + kk * 32);
            #pragma unroll
            for (int p = 0; p < 4; p++) {
                uint32_t b[4];
                ldsm4(b, bB1 + p * (16 * 240) + kk * 32);
                mma16816h(acc[0][2 * p],     aA, b[0], b[1]);
                mma16816h(acc[0][2 * p + 1], aA, b[2], b[3]);
                mma16816h(acc[1][2 * p],     aB, b[0], b[1]);
                mma16816h(acc[1][2 * p + 1], aB, b[2], b[3]);
            }
        }
        __syncwarp();   // A-LDSM done; XS free next iteration

        // ================= layer 2: JIT sins pipelined one kk-step ahead ========
        uint32_t ac2[2][8][2];
        #pragma unroll
        for (int nt = 0; nt < 8; nt++) {
            uint32_t bw = B2P[nt * 4 + tig];
            ac2[0][nt][0] = bw; ac2[0][nt][1] = bw;
            ac2[1][nt][0] = bw; ac2[1][nt][1] = bw;
        }
        uint32_t ahC[2][2][2];
        #pragma unroll
        for (int mt = 0; mt < 2; mt++)
            #pragma unroll
            for (int q = 0; q < 2; q++) {
                ahC[mt][q][0] = sinpk(acc[mt][q][0]);
                ahC[mt][q][1] = sinpk(acc[mt][q][1]);
            }
        #pragma unroll
        for (int kk = 0; kk < 4; kk++) {
            uint32_t ahN[2][2][2];
            if (kk < 3) {           // MUFU stream for kk+1
                #pragma unroll
                for (int mt = 0; mt < 2; mt++)
                    #pragma unroll
                    for (int q = 0; q < 2; q++) {
                        ahN[mt][q][0] = sinpk(acc[mt][2 * kk + 2 + q][0]);
                        ahN[mt][q][1] = sinpk(acc[mt][2 * kk + 2 + q][1]);
                    }
            }
            #pragma unroll
            for (int p = 0; p < 4; p++) {   // tensor stream for kk
                uint32_t b[4];
                ldsm4(b, bB2 + p * (16 * 144) + kk * 32);
                #pragma unroll
                for (int mt = 0; mt < 2; mt++) {
                    uint32_t a[4] = { ahC[mt][0][0], ahC[mt][0][1],
                                      ahC[mt][1][0], ahC[mt][1][1] };
                    mma16816h(ac2[mt][2 * p],     a, b[0], b[1]);
                    mma16816h(ac2[mt][2 * p + 1], a, b[2], b[3]);
                }
            }
            if (kk < 3) {
                #pragma unroll
                for (int mt = 0; mt < 2; mt++)
                    #pragma unroll
                    for (int q = 0; q < 2; q++) {
                        ahC[mt][q][0] = ahN[mt][q][0];
                        ahC[mt][q][1] = ahN[mt][q][1];
                    }
            }
        }

        // ================= layer 3: same JIT pipeline over ac2 =================
        float c0[4] = { i3a, i3b, i3a, i3b };
        float c1[4] = { i3a, i3b, i3a, i3b };
        #pragma unroll
        for (int mt = 0; mt < 2; mt++)
            #pragma unroll
            for (int q = 0; q < 2; q++) {
                ahC[mt][q][0] = sinpk(ac2[mt][q][0]);
                ahC[mt][q][1] = sinpk(ac2[mt][q][1]);
            }
        #pragma unroll
        for (int kk = 0; kk < 4; kk++) {
            uint32_t ahN[2][2][2];
            if (kk < 3) {
                #pragma unroll
                for (int mt = 0; mt < 2; mt++)
                    #pragma unroll
                    for (int q = 0; q < 2; q++) {
                        ahN[mt][q][0] = sinpk(ac2[mt][2 * kk + 2 + q][0]);
                        ahN[mt][q][1] = sinpk(ac2[mt][2 * kk + 2 + q][1]);
                    }
            }
            {
                uint32_t a0[4] = { ahC[0][0][0], ahC[0][0][1], ahC[0][1][0], ahC[0][1][1] };
                uint32_t a1[4] = { ahC[1][0][0], ahC[1][0][1], ahC[1][1][0], ahC[1][1][1] };
                mma16816f(c0, a0, B3f[kk][0], B3f[kk][1]);
                mma16816f(c1, a1, B3f[kk][0], B3f[kk][1]);
            }
            if (kk < 3) {
                #pragma unroll
                for (int mt = 0; mt < 2; mt++)
                    #pragma unroll
                    for (int q = 0; q < 2; q++) {
                        ahC[mt][q][0] = ahN[mt][q][0];
                        ahC[mt][q][1] = ahN[mt][q][1];
                    }
            }
        }

        // ================= residual + store =================
        #pragma unroll
        for (int mt = 0; mt < 2; mt++) {
            const float* c = (mt == 0) ? c0 : c1;
            float bxA = __shfl_sync(0xffffffffu, bx, mt * 16 + g);
            float byA = __shfl_sync(0xffffffffu, by, mt * 16 + g);
            float bzA = __shfl_sync(0xffffffffu, bz, mt * 16 + g);
            float bxB = __shfl_sync(0xffffffffu, bx, mt * 16 + g + 8);
            float byB = __shfl_sync(0xffffffffu, by, mt * 16 + g + 8);
            float bzB = __shfl_sync(0xffffffffu, bz, mt * 16 + g + 8);

            int rA = tile * 128 + warpRow + mt * 16 + g;
            int rB = rA + 8;
            if (tig == 0) {      // C cols 0,1 = out.x, out.y
                out[rA * 3 + 0] = bxA + c[0];
                out[rA * 3 + 1] = byA + c[1];
                out[rB * 3 + 0] = bxB + c[2];
                out[rB * 3 + 1] = byB + c[3];
            } else if (tig == 1) {  // C col 2 = out.z
                out[rA * 3 + 2] = bzA + c[0];
                out[rB * 3 + 2] = bzB + c[2];
            }
        }
        __syncwarp();   // XS reads done before next tile's features overwrite
    }
}

extern "C" void kernel_launch(void* const* d_in, const int* in_sizes, int n_in,
                              void* d_out, int out_size) {
    const float* bases   = (const float*)d_in[0];
    const float* normals = (const float*)d_in[1];
    const float* enc     = (const float*)d_in[2];
    const float* W1      = (const float*)d_in[3];
    const float* b1      = (const float*)d_in[4];
    const float* W2      = (const float*)d_in[5];
    const float* b2      = (const float*)d_in[6];
    const float* W3      = (const float*)d_in[7];
    const float* b3      = (const float*)d_in[8];
    float* out = (float*)d_out;

    cudaFuncSetAttribute(fused_encode_mlp,
                         cudaFuncAttributeMaxDynamicSharedMemorySize, SMEM_BYTES);

    // persistent: 148 SMs x 4 CTAs (smem-limited, 16 warps/SM)
    fused_encode_mlp<<<592, 128, SMEM_BYTES>>>(bases, normals, enc,
                                               W1, b1, W2, b2, W3, b3, out);
}